// round 6
// baseline (speedup 1.0000x reference)
#include <cuda_runtime.h>
#include <math.h>

#define FM_C 256
#define FM_H 200
#define FM_W 200
#define IIH 201
#define IIW 201
#define NBOX 1024
#define OH 7
#define OW 7
#define NBINS 49

// Integral image scratch, channel-last layout: [y][x][c], y,x in 0..200.
__device__ float g_ii[IIH * IIW * FM_C];      // 41.4 MB
// Full y-cumsum through fm row 99, per (fm x, c): segment-boundary offset.
__device__ float g_bound[FM_W * FM_C];        // 204 KB

// ---------------------------------------------------------------------------
// K1: y-cumsum fused with transpose [C][H][W] -> [y+1][x+1][C], split into
// 2 y-segments of 100 rows (416 blocks). Seg-0 also writes its final
// accumulator row to g_bound; k2 applies the fixup for rows 101..200.
// YC=10 rows per barrier (10 chunks/segment); depth-2 chunk prefetch.
// ---------------------------------------------------------------------------
#define TX 16
#define TC 16
#define YC 10
#define SEGROWS 100
#define NCHUNK (SEGROWS / YC)   // 10

__global__ void __launch_bounds__(256) k1_ycum_transpose(const float* __restrict__ fm) {
    __shared__ float sh[2][YC][TC][TX + 1];
    const int tid = threadIdx.x;           // 0..255
    const int x0 = blockIdx.x * TX;
    const int c0 = blockIdx.y * TC;
    const int seg = blockIdx.z;            // 0 or 1
    const int ybase = seg * SEGROWS;

    // Load-side mapping: contiguous x within a 16-thread group
    const int xx = tid & (TX - 1);         // 0..15
    const int cc = tid >> 4;               // 0..15
    const int xr = x0 + xx;
    const bool valid = (xr < FM_W);
    const float* src = fm + (size_t)(c0 + cc) * (FM_H * FM_W)
                          + (size_t)ybase * FM_W + xr;

    // Store-side mapping: contiguous c within a 16-thread group
    const int c_out = tid & 15;
    const int x_out = tid >> 4;
    const bool validw = (x0 + x_out) < FM_W;
    float* dstbase = g_ii + (size_t)(x0 + x_out + 1) * FM_C + (c0 + c_out);

    // --- zero pads (seg 0 blocks only) ---
    if (seg == 0) {
        if (validw) {
            g_ii[(size_t)(x0 + x_out + 1) * FM_C + (c0 + c_out)] = 0.0f;  // y=0 plane
        }
        if (blockIdx.x == 0) {
            for (int idx = tid; idx < IIH * TC; idx += 256) {
                const int y = idx / TC;
                const int c = idx - y * TC;
                g_ii[((size_t)y * IIW) * FM_C + (c0 + c)] = 0.0f;         // x=0 column
            }
        }
    }

    float b0[YC], b1[YC];
    #pragma unroll
    for (int k = 0; k < YC; k++) {
        b0[k] = valid ? __ldcs(&src[(0 * YC + k) * FM_W]) : 0.0f;
        b1[k] = valid ? __ldcs(&src[(1 * YC + k) * FM_W]) : 0.0f;
    }

    float acc = 0.0f;
    #pragma unroll 1
    for (int ch = 0; ch < NCHUNK; ch++) {
        const int buf = ch & 1;
        #pragma unroll
        for (int k = 0; k < YC; k++) {
            acc += b0[k];
            sh[buf][k][cc][xx] = acc;
        }
        // rotate; prefetch chunk ch+2 (evict-first: fm never reused)
        #pragma unroll
        for (int k = 0; k < YC; k++) b0[k] = b1[k];
        {
            const int rb = (ch + 2) * YC;
            #pragma unroll
            for (int k = 0; k < YC; k++) {
                const int r = rb + k;
                b1[k] = (valid && r < SEGROWS) ? __ldcs(&src[r * FM_W]) : 0.0f;
            }
        }
        __syncthreads();
        if (validw) {
            const size_t rowbase = (size_t)(ybase + ch * YC + 1) * (IIW * FM_C);
            #pragma unroll
            for (int k = 0; k < YC; k++) {
                dstbase[rowbase + (size_t)k * (IIW * FM_C)] = sh[buf][k][c_out][x_out];
            }
        }
        // double buffer: this buffer is rewritten only after the next barrier,
        // which follows all its reads.
    }

    // Seg-0: emit boundary row (full y-cumsum through fm row 99) for k2 fixup.
    if (seg == 0 && valid) {
        g_bound[xr * FM_C + (c0 + cc)] = acc;
    }
}

// ---------------------------------------------------------------------------
// K2: x-cumsum in-place, channel-last. 400 blocks (200 y-rows x 2 c-halves),
// 128 threads. Rows y>=101 add the segment-boundary offset during the load
// batch. Double-buffered batches hide L2 latency.
// ---------------------------------------------------------------------------
#define K2B 20
#define K2NB (FM_W / K2B)    // 10
__global__ void __launch_bounds__(128) k2_xcum() {
    const int y = blockIdx.x + 1;                    // 1..200
    const int c = blockIdx.y * 128 + threadIdx.x;    // 0..255
    float* row = g_ii + (size_t)(y * IIW) * FM_C + c;
    const float* bnd = g_bound + c;                  // bound[fm x][c]
    const bool fix = (y >= SEGROWS + 1);             // rows 101..200

    float va[K2B], vb[K2B];
    #pragma unroll
    for (int j = 0; j < K2B; j++) {
        va[j] = row[(size_t)(1 + j) * FM_C];
        if (fix) va[j] += bnd[(size_t)j * FM_C];
    }

    float acc = 0.0f;
    #pragma unroll 1
    for (int i = 0; i < K2NB; i++) {
        if (i + 1 < K2NB) {
            const int xb = 1 + (i + 1) * K2B;        // ii col; fm col = xb-1
            #pragma unroll
            for (int j = 0; j < K2B; j++) {
                vb[j] = row[(size_t)(xb + j) * FM_C];
                if (fix) vb[j] += bnd[(size_t)(xb - 1 + j) * FM_C];
            }
        }
        const int x0_ = 1 + i * K2B;
        #pragma unroll
        for (int j = 0; j < K2B; j++) {
            acc += va[j];
            row[(size_t)(x0_ + j) * FM_C] = acc;
        }
        #pragma unroll
        for (int j = 0; j < K2B; j++) va[j] = vb[j];
    }
}

// ---------------------------------------------------------------------------
// K3: gather. One block per TWO boxes (512 blocks, single wave).
// Double-buffered staging: writeback of pass p overlaps gather of pass p+1,
// one __syncthreads per pass. Output stores evict-first (.cs).
// ---------------------------------------------------------------------------
#define S_PAD 25
#define BPB 2   // boxes per block

template <int NB, int BIN0>
__device__ __forceinline__ void gather_bins(const float4* __restrict__ ii4,
                                            const int* __restrict__ soff,
                                            const float* __restrict__ srarea,
                                            float* __restrict__ sh,
                                            int tid) {
    const int warp = tid >> 5;
    const int lane = tid & 31;
    const int cg = warp * 8 + (lane & 7);   // 0..63 channel group (float4)
    const int bsl = lane >> 3;              // 0..3 bin slot

    #pragma unroll
    for (int bb = bsl; bb < NB; bb += 4) {
        const int b = BIN0 + bb;
        const int o0 = soff[b * 4 + 0];
        const int o1 = soff[b * 4 + 1];
        const int o2 = soff[b * 4 + 2];
        const int o3 = soff[b * 4 + 3];
        const float4 A = ii4[o0 + cg];
        const float4 B = ii4[o1 + cg];
        const float4 C = ii4[o2 + cg];
        const float4 D = ii4[o3 + cg];
        const float ra = srarea[b];
        const int cb = cg * 4;
        sh[(cb + 0) * S_PAD + bb] = (A.x - B.x - C.x + D.x) * ra;
        sh[(cb + 1) * S_PAD + bb] = (A.y - B.y - C.y + D.y) * ra;
        sh[(cb + 2) * S_PAD + bb] = (A.z - B.z - C.z + D.z) * ra;
        sh[(cb + 3) * S_PAD + bb] = (A.w - B.w - C.w + D.w) * ra;
    }
}

template <int NB, int BIN0>
__device__ __forceinline__ void write_bins(const float* __restrict__ sh,
                                           float* __restrict__ outn,
                                           int tid) {
    #pragma unroll 4
    for (int idx = tid; idx < FM_C * NB; idx += 256) {
        const int c = idx / NB;               // NB constexpr -> magic multiply
        const int b = idx - c * NB;
        __stcs(&outn[c * NBINS + BIN0 + b], sh[c * S_PAD + b]);
    }
}

__global__ void __launch_bounds__(256) k3_gather(const float* __restrict__ boxes,
                                                 float* __restrict__ out) {
    __shared__ float sh0[FM_C * S_PAD];      // 25.6 KB
    __shared__ float sh1[FM_C * S_PAD];      // 25.6 KB
    __shared__ int   soff[BPB][NBINS * 4];
    __shared__ float srarea[BPB][NBINS];
    const int tid = threadIdx.x;

    if (tid < BPB * NBINS) {
        const int bx = tid / NBINS;
        const int bin = tid - bx * NBINS;
        const int n = blockIdx.x * BPB + bx;

        const float bx1 = __ldg(&boxes[n * 4 + 0]);
        const float by1 = __ldg(&boxes[n * 4 + 1]);
        const float bx2 = __ldg(&boxes[n * 4 + 2]);
        const float by2 = __ldg(&boxes[n * 4 + 3]);

        // scale = 200/800 = 0.25 exactly (bit-exact with reference)
        const int b0 = (int)floorf(bx1 * 0.25f);
        const int b1 = (int)floorf(by1 * 0.25f);
        const int b2 = (int)floorf(bx2 * 0.25f);
        const int b3 = (int)floorf(by2 * 0.25f);

        const int x1 = min(max(b0, 0), FM_W - 1);
        const int y1 = min(max(b1, 0), FM_H - 1);
        const int x2 = min(max(b2 + 1, x1 + 1), FM_W);
        const int y2 = min(max(b3 + 1, y1 + 1), FM_H);
        const int rh = y2 - y1;
        const int rw = x2 - x1;

        const int i = bin / OW;
        const int j = bin - i * OW;
        const int rs_ = y1 + (i * rh) / OH;
        const int re_ = y1 + ((i + 1) * rh + OH - 1) / OH;
        const int cs_ = x1 + (j * rw) / OW;
        const int ce_ = x1 + ((j + 1) * rw + OW - 1) / OW;

        soff[bx][bin * 4 + 0] = (re_ * IIW + ce_) * (FM_C / 4);
        soff[bx][bin * 4 + 1] = (rs_ * IIW + ce_) * (FM_C / 4);
        soff[bx][bin * 4 + 2] = (re_ * IIW + cs_) * (FM_C / 4);
        soff[bx][bin * 4 + 3] = (rs_ * IIW + cs_) * (FM_C / 4);
        srarea[bx][bin] = 1.0f / (float)((re_ - rs_) * (ce_ - cs_));
    }
    __syncthreads();

    const float4* ii4 = (const float4*)g_ii;
    float* out0 = out + (size_t)(blockIdx.x * BPB + 0) * (FM_C * NBINS);
    float* out1 = out + (size_t)(blockIdx.x * BPB + 1) * (FM_C * NBINS);

    // Pipelined: G0 | S | W0 G1 | S | W1 G2 | S | W2 G3 | S | W3
    gather_bins<25, 0>(ii4, soff[0], srarea[0], sh0, tid);
    __syncthreads();
    write_bins<25, 0>(sh0, out0, tid);
    gather_bins<24, 25>(ii4, soff[0], srarea[0], sh1, tid);
    __syncthreads();
    write_bins<24, 25>(sh1, out0, tid);
    gather_bins<25, 0>(ii4, soff[1], srarea[1], sh0, tid);
    __syncthreads();
    write_bins<25, 0>(sh0, out1, tid);
    gather_bins<24, 25>(ii4, soff[1], srarea[1], sh1, tid);
    __syncthreads();
    write_bins<24, 25>(sh1, out1, tid);
}

// ---------------------------------------------------------------------------
extern "C" void kernel_launch(void* const* d_in, const int* in_sizes, int n_in,
                              void* d_out, int out_size) {
    const float* fm    = (const float*)d_in[0];   // [1,256,200,200] fp32
    const float* boxes = (const float*)d_in[1];   // [1024,4] fp32
    float* out = (float*)d_out;                   // [1024,256,7,7] fp32

    {
        dim3 grid((FM_W + TX - 1) / TX, FM_C / TC, 2);  // (13, 16, 2) = 416 blocks
        k1_ycum_transpose<<<grid, 256>>>(fm);
    }
    {
        dim3 grid(FM_H, 2);                             // 400 blocks
        k2_xcum<<<grid, 128>>>();
    }
    k3_gather<<<NBOX / BPB, 256>>>(boxes, out);
}